// round 14
// baseline (speedup 1.0000x reference)
#include <cuda_runtime.h>
#include <math_constants.h>
#include <cstdint>

#define BATCH  4
#define SEQ    2048
#define DIM    1024
#define HEADS  16
#define GROUPS 4
#define DHEAD  64
#define KVD    512
#define M_ROWS (BATCH*SEQ)      /* 8192 */
#define QKV_N  (DIM + KVD)      /* 1536 */

// Scratch (allocation-free rule: __device__ globals). All tf32-pre-rounded.
__device__ float g_xn  [M_ROWS * DIM];
__device__ float g_qkv [M_ROWS * QKV_N];
__device__ float g_ao  [M_ROWS * DIM];
__device__ float g_wq  [DIM * DIM];
__device__ float g_wkv [DIM * KVD];
__device__ float g_wout[DIM * DIM];

// ---------------------------------------------------------------------------
// helpers
// ---------------------------------------------------------------------------
__device__ __forceinline__ float tf32r(float x) {
    uint32_t u;
    asm("cvt.rna.tf32.f32 %0, %1;" : "=r"(u) : "f"(x));
    return __uint_as_float(u);
}
__device__ __forceinline__ float4 tf32r4(float4 f) {
    f.x = tf32r(f.x); f.y = tf32r(f.y); f.z = tf32r(f.z); f.w = tf32r(f.w);
    return f;
}
__device__ __forceinline__ void mma8(float* c, const uint32_t* a, const uint32_t* b) {
    asm volatile(
        "mma.sync.aligned.m16n8k8.row.col.f32.tf32.tf32.f32 "
        "{%0,%1,%2,%3}, {%4,%5,%6,%7}, {%8,%9}, {%0,%1,%2,%3};\n"
        : "+f"(c[0]), "+f"(c[1]), "+f"(c[2]), "+f"(c[3])
        : "r"(a[0]), "r"(a[1]), "r"(a[2]), "r"(a[3]), "r"(b[0]), "r"(b[1]));
}
__device__ __forceinline__ uint32_t fbits(float x) { return __float_as_uint(x); }

__device__ __forceinline__ void cpa16(uint32_t dst, const float* src) {
    asm volatile("cp.async.cg.shared.global [%0], [%1], 16;\n" :: "r"(dst), "l"(src));
}
#define CP_COMMIT() asm volatile("cp.async.commit_group;\n" ::: "memory")
template<int N> __device__ __forceinline__ void cp_wait() {
    asm volatile("cp.async.wait_group %0;\n" :: "n"(N) : "memory");
}

#define SCALE_LOG2E 0.18033688011112042f   /* 0.125 * log2(e) */

// ---------------------------------------------------------------------------
// Kernel 0: round weights into tf32 copies
// ---------------------------------------------------------------------------
__global__ void __launch_bounds__(256) round_weights(const float* __restrict__ Wq,
                                                     const float* __restrict__ Wkv,
                                                     const float* __restrict__ Wout) {
    int i = (blockIdx.x * 256 + threadIdx.x) * 4;
    const int NQ = DIM * DIM, NKV = DIM * KVD;
    if (i < NQ) {
        *(float4*)(g_wq + i) = tf32r4(*(const float4*)(Wq + i));
    } else if (i < NQ + NKV) {
        int j = i - NQ;
        *(float4*)(g_wkv + j) = tf32r4(*(const float4*)(Wkv + j));
    } else {
        int j = i - NQ - NKV;
        if (j < DIM * DIM)
            *(float4*)(g_wout + j) = tf32r4(*(const float4*)(Wout + j));
    }
}

// ---------------------------------------------------------------------------
// Kernel 1: row LayerNorm over DIM=1024, tf32-rounded output
// ---------------------------------------------------------------------------
__global__ void __launch_bounds__(256) ln_rows(const float* __restrict__ x,
                                               const float* __restrict__ sc,
                                               const float* __restrict__ bi) {
    int row = blockIdx.x;
    const float* xr = x + (size_t)row * DIM;
    float v[4];
    float s = 0.f, s2 = 0.f;
#pragma unroll
    for (int i = 0; i < 4; i++) {
        v[i] = xr[threadIdx.x + i * 256];
        s += v[i]; s2 += v[i] * v[i];
    }
    __shared__ float rs[8], rq[8];
#pragma unroll
    for (int o = 16; o; o >>= 1) {
        s  += __shfl_xor_sync(0xffffffffu, s,  o);
        s2 += __shfl_xor_sync(0xffffffffu, s2, o);
    }
    int warp = threadIdx.x >> 5, lane = threadIdx.x & 31;
    if (!lane) { rs[warp] = s; rq[warp] = s2; }
    __syncthreads();
    if (threadIdx.x == 0) {
        float a = 0.f, b = 0.f;
#pragma unroll
        for (int w = 0; w < 8; w++) { a += rs[w]; b += rq[w]; }
        rs[0] = a; rq[0] = b;
    }
    __syncthreads();
    float mu = rs[0] * (1.f / DIM);
    float r  = rsqrtf(rq[0] * (1.f / DIM) - mu * mu + 1e-6f);
    float* o = g_xn + (size_t)row * DIM;
#pragma unroll
    for (int i = 0; i < 4; i++) {
        int c = threadIdx.x + i * 256;
        o[c] = tf32r((v[i] - mu) * r * sc[c] + bi[c]);
    }
}

// ---------------------------------------------------------------------------
// tf32 GEMM: 128x128 block tile, 4-stage cp.async pipeline, 8 warps (4x2),
// warp tile 32m x 64n. __launch_bounds__(256,2) -> 2 CTAs/SM.
// As row-major stride 20; Bs k-major stride 136. Dynamic smem 75776 B.
// ---------------------------------------------------------------------------
#define GSTAGES 4
#define GA_ST 2560              /* floats per A stage: 128*20 */
#define GB_ST 2176              /* floats per B stage: 16*136 */
#define GEMM_SMEM (GSTAGES * (GA_ST + GB_ST) * 4)   /* 75776 bytes */

__device__ __forceinline__ void mmgemm(const float* __restrict__ A, int lda,
                                       const float* __restrict__ Bp, int ldb,
                                       float* __restrict__ C, int ldc,
                                       int rowbase, int colb, int colc) {
    extern __shared__ float smg[];
    float (*As)[128][20] = (float (*)[128][20])smg;
    float (*Bs)[16][136] = (float (*)[16][136])(smg + GSTAGES * GA_ST);
    int tid = threadIdx.x, lane = tid & 31, w = tid >> 5;
    int l4 = lane >> 2, lm4 = lane & 3;
    int m0w = 32 * (w & 3), n0w = 64 * (w >> 2);
    uint32_t aB = (uint32_t)__cvta_generic_to_shared(smg);
    uint32_t bB = (uint32_t)__cvta_generic_to_shared(smg + GSTAGES * GA_ST);

    float Cf[2][8][4];
#pragma unroll
    for (int mt = 0; mt < 2; mt++)
#pragma unroll
        for (int nt = 0; nt < 8; nt++)
#pragma unroll
            for (int i = 0; i < 4; i++) Cf[mt][nt][i] = 0.f;

    const int NIT = DIM / 16;   // K = 1024 for both GEMMs

#define GFILL(k0, st)                                                          \
    {                                                                          \
        _Pragma("unroll")                                                      \
        for (int t = 0; t < 2; t++) {                                          \
            int idx = tid + t * 256;                 /* 0..511 */              \
            int ra = idx >> 2, ca = (idx & 3) * 4;                             \
            cpa16(aB + (uint32_t)((st) * GA_ST + ra * 20 + ca) * 4,            \
                  A + (size_t)(rowbase + ra) * lda + (k0) + ca);               \
            int rb = idx >> 5, cb = (idx & 31) * 4;                            \
            cpa16(bB + (uint32_t)((st) * GB_ST + rb * 136 + cb) * 4,           \
                  Bp + (size_t)((k0) + rb) * ldb + colb + cb);                 \
        }                                                                      \
        CP_COMMIT();                                                           \
    }

    // prologue: 3 stages in flight
    GFILL(0, 0);
    GFILL(16, 1);
    GFILL(32, 2);
    for (int it = 0; it < NIT; it++) {
        int s = it & 3;
        if (it + 3 < NIT) { GFILL((it + 3) * 16, (it + 3) & 3); cp_wait<3>(); }
        else              { cp_wait<0>(); }
        __syncthreads();
#pragma unroll
        for (int ks = 0; ks < 2; ks++) {
            uint32_t af[2][4];
#pragma unroll
            for (int mt = 0; mt < 2; mt++) {
                int m = m0w + 16 * mt;
                af[mt][0] = fbits(As[s][m + l4    ][8 * ks + lm4]);
                af[mt][1] = fbits(As[s][m + l4 + 8][8 * ks + lm4]);
                af[mt][2] = fbits(As[s][m + l4    ][8 * ks + lm4 + 4]);
                af[mt][3] = fbits(As[s][m + l4 + 8][8 * ks + lm4 + 4]);
            }
#pragma unroll
            for (int nt = 0; nt < 8; nt++) {
                uint32_t bf[2];
                bf[0] = fbits(Bs[s][8 * ks + lm4    ][n0w + 8 * nt + l4]);
                bf[1] = fbits(Bs[s][8 * ks + lm4 + 4][n0w + 8 * nt + l4]);
                mma8(Cf[0][nt], af[0], bf);
                mma8(Cf[1][nt], af[1], bf);
            }
        }
        __syncthreads();
    }
#undef GFILL
#pragma unroll
    for (int mt = 0; mt < 2; mt++)
#pragma unroll
        for (int nt = 0; nt < 8; nt++) {
            int r = rowbase + m0w + 16 * mt + l4;
            int c = colc + n0w + 8 * nt + 2 * lm4;
            *(float2*)&C[(size_t)r * ldc + c] =
                make_float2(Cf[mt][nt][0], Cf[mt][nt][1]);
            *(float2*)&C[(size_t)(r + 8) * ldc + c] =
                make_float2(Cf[mt][nt][2], Cf[mt][nt][3]);
        }
}

__global__ void __launch_bounds__(256, 2) gemm_qkv() {
    int nb = blockIdx.x;
    int rb = blockIdx.y * 128;
    const float* Bp; int ldb, colb;
    if (nb < 8) { Bp = g_wq;  ldb = DIM; colb = nb * 128; }
    else        { Bp = g_wkv; ldb = KVD; colb = (nb - 8) * 128; }
    mmgemm(g_xn, DIM, Bp, ldb, g_qkv, QKV_N, rb, colb, nb * 128);
}

__global__ void __launch_bounds__(256, 2) gemm_out(float* __restrict__ out) {
    mmgemm(g_ao, DIM, g_wout, DIM, out, DIM,
           blockIdx.y * 128, blockIdx.x * 128, blockIdx.x * 128);
}

// ---------------------------------------------------------------------------
// Kernel 3: per-head LN, warp-per-(row,seg), 256-thread blocks.
// seg 0..15 = q heads (x 0.125*log2e), 16..19 = k groups, 20..23 = v (round only)
// ---------------------------------------------------------------------------
__global__ void __launch_bounds__(256) head_ln(const float* __restrict__ qs,
                                               const float* __restrict__ qb,
                                               const float* __restrict__ ks,
                                               const float* __restrict__ kb) {
    int w = threadIdx.x >> 5, lane = threadIdx.x & 31;
    int row = blockIdx.x * 8 + w, seg = blockIdx.y;
    if (seg >= 20) {
        float* p = g_qkv + (size_t)row * QKV_N + DIM + KVD / 2 + (seg - 20) * DHEAD;
        p[lane]      = tf32r(p[lane]);
        p[lane + 32] = tf32r(p[lane + 32]);
        return;
    }
    bool isq = seg < 16;
    int col0 = isq ? seg * DHEAD : DIM + (seg - 16) * DHEAD;
    const float* sc = isq ? qs : ks;
    const float* bb = isq ? qb : kb;
    float* p = g_qkv + (size_t)row * QKV_N + col0;
    float a = p[lane], c = p[lane + 32];
    float s = a + c, s2 = a * a + c * c;
#pragma unroll
    for (int o = 16; o; o >>= 1) {
        s  += __shfl_xor_sync(0xffffffffu, s,  o);
        s2 += __shfl_xor_sync(0xffffffffu, s2, o);
    }
    float mu = s * (1.f / 64.f);
    float r  = rsqrtf(s2 * (1.f / 64.f) - mu * mu + 1e-6f);
    float mult = isq ? SCALE_LOG2E : 1.0f;
    p[lane]      = tf32r(((a - mu) * r * sc[lane]      + bb[lane])      * mult);
    p[lane + 32] = tf32r(((c - mu) * r * sc[lane + 32] + bb[lane + 32]) * mult);
}

// ---------------------------------------------------------------------------
// Kernel 4: flash attention, tf32 mma, register-resident softmax.
// Block = 256 q rows x (b,h). 8 warps, each warp: 32 q rows x ALL 64 keys.
// (unchanged from R12 — protect the win)
// ---------------------------------------------------------------------------
#define AT_STAGE (2 * 64 * 68)              /* floats per stage (K + V) */
#define ATTN_SMEM (2 * AT_STAGE * 4)        /* 69632 bytes */

__global__ void __launch_bounds__(256, 1) attn_kernel() {
    extern __shared__ float sm[];
    int tid = threadIdx.x, lane = tid & 31, w = tid >> 5;
    int l4 = lane >> 2, lm4 = lane & 3;
    int qt = blockIdx.x, bh = blockIdx.y;
    int b = bh >> 4, h = bh & 15, g = h >> 2;
    uint32_t smb = (uint32_t)__cvta_generic_to_shared(sm);

    // ---- stage Q (256 rows x 64) across both stage regions, hoist frags ----
    const float* qsrc = g_qkv + (size_t)(b * SEQ + qt * 256) * QKV_N + h * DHEAD;
#pragma unroll
    for (int i = 0; i < 16; i++) {
        int idx = tid + i * 256;
        int r = idx >> 4, c = (idx & 15) * 4;
        cpa16(smb + (uint32_t)(r * 68 + c) * 4, qsrc + (size_t)r * QKV_N + c);
    }
    CP_COMMIT(); cp_wait<0>();
    __syncthreads();

    uint32_t Qf[2][8][4];
#pragma unroll
    for (int mt = 0; mt < 2; mt++) {
        int r0 = 32 * w + 16 * mt + l4;
#pragma unroll
        for (int ks = 0; ks < 8; ks++) {
            Qf[mt][ks][0] = fbits(sm[(r0    ) * 68 + 8 * ks + lm4]);
            Qf[mt][ks][1] = fbits(sm[(r0 + 8) * 68 + 8 * ks + lm4]);
            Qf[mt][ks][2] = fbits(sm[(r0    ) * 68 + 8 * ks + lm4 + 4]);
            Qf[mt][ks][3] = fbits(sm[(r0 + 8) * 68 + 8 * ks + lm4 + 4]);
        }
    }
    __syncthreads();

    const float* kb0 = g_qkv + (size_t)(b * SEQ) * QKV_N + DIM + g * DHEAD;
    const float* vb0 = kb0 + KVD / 2;

#define KVFILL(kt, st)                                                         \
    {                                                                          \
        const float* kbp = kb0 + (size_t)(kt) * 64 * QKV_N;                    \
        const float* vbp = vb0 + (size_t)(kt) * 64 * QKV_N;                    \
        uint32_t base = smb + (uint32_t)(st) * AT_STAGE * 4;                   \
        _Pragma("unroll")                                                      \
        for (int i = 0; i < 4; i++) {                                          \
            int idx = tid + i * 256;                                           \
            int r = idx >> 4, c = (idx & 15) * 4;                              \
            cpa16(base + (uint32_t)(r * 68 + c) * 4,                           \
                  kbp + (size_t)r * QKV_N + c);                                \
            cpa16(base + (uint32_t)(64 * 68 + r * 68 + c) * 4,                 \
                  vbp + (size_t)r * QKV_N + c);                                \
        }                                                                      \
        CP_COMMIT();                                                           \
    }

    KVFILL(0, 0);

    float Of[2][8][4];
#pragma unroll
    for (int mt = 0; mt < 2; mt++)
#pragma unroll
        for (int nt = 0; nt < 8; nt++)
#pragma unroll
            for (int i = 0; i < 4; i++) Of[mt][nt][i] = 0.f;
    float mS[2][2], lS[2][2];
#pragma unroll
    for (int mt = 0; mt < 2; mt++) {
        mS[mt][0] = -CUDART_INF_F; mS[mt][1] = -CUDART_INF_F;
        lS[mt][0] = 0.f;           lS[mt][1] = 0.f;
    }

    int srcA = (l4 << 2) | (lm4 >> 1);
    int srcB = srcA + 2;
    bool odd = lm4 & 1;

    const int NT = SEQ / 64;
    for (int kt = 0; kt < NT; kt++) {
        int s = kt & 1;
        if (kt + 1 < NT) { KVFILL(kt + 1, s ^ 1); cp_wait<1>(); }
        else             { cp_wait<0>(); }
        __syncthreads();

        const float* Ks = sm + s * AT_STAGE;
        const float* Vs = Ks + 64 * 68;

        // ---- S = Q K^T; K fragments shared across both mt tiles ----
        float Sa[2][8][4];
#pragma unroll
        for (int mt = 0; mt < 2; mt++)
#pragma unroll
            for (int nt = 0; nt < 8; nt++)
#pragma unroll
                for (int i = 0; i < 4; i++) Sa[mt][nt][i] = 0.f;
#pragma unroll
        for (int ks = 0; ks < 8; ks++)
#pragma unroll
            for (int nt = 0; nt < 8; nt++) {
                uint32_t bf[2];
                int key = 8 * nt + l4;
                bf[0] = fbits(Ks[key * 68 + 8 * ks + lm4]);
                bf[1] = fbits(Ks[key * 68 + 8 * ks + lm4 + 4]);
                mma8(Sa[0][nt], Qf[0][ks], bf);
                mma8(Sa[1][nt], Qf[1][ks], bf);
            }

        // ---- warp-local online softmax, per mt tile ----
#pragma unroll
        for (int mt = 0; mt < 2; mt++) {
            float pm0 = -CUDART_INF_F, pm1 = -CUDART_INF_F;
#pragma unroll
            for (int nt = 0; nt < 8; nt++) {
                pm0 = fmaxf(pm0, fmaxf(Sa[mt][nt][0], Sa[mt][nt][1]));
                pm1 = fmaxf(pm1, fmaxf(Sa[mt][nt][2], Sa[mt][nt][3]));
            }
            pm0 = fmaxf(pm0, __shfl_xor_sync(0xffffffffu, pm0, 1));
            pm0 = fmaxf(pm0, __shfl_xor_sync(0xffffffffu, pm0, 2));
            pm1 = fmaxf(pm1, __shfl_xor_sync(0xffffffffu, pm1, 1));
            pm1 = fmaxf(pm1, __shfl_xor_sync(0xffffffffu, pm1, 2));
            float mn0 = fmaxf(mS[mt][0], pm0), mn1 = fmaxf(mS[mt][1], pm1);
            float al0 = exp2f(mS[mt][0] - mn0), al1 = exp2f(mS[mt][1] - mn1);
            mS[mt][0] = mn0; mS[mt][1] = mn1;
            float s0 = 0.f, s1 = 0.f;
#pragma unroll
            for (int nt = 0; nt < 8; nt++) {
                Sa[mt][nt][0] = exp2f(Sa[mt][nt][0] - mn0); s0 += Sa[mt][nt][0];
                Sa[mt][nt][1] = exp2f(Sa[mt][nt][1] - mn0); s0 += Sa[mt][nt][1];
                Sa[mt][nt][2] = exp2f(Sa[mt][nt][2] - mn1); s1 += Sa[mt][nt][2];
                Sa[mt][nt][3] = exp2f(Sa[mt][nt][3] - mn1); s1 += Sa[mt][nt][3];
            }
            s0 += __shfl_xor_sync(0xffffffffu, s0, 1);
            s0 += __shfl_xor_sync(0xffffffffu, s0, 2);
            s1 += __shfl_xor_sync(0xffffffffu, s1, 1);
            s1 += __shfl_xor_sync(0xffffffffu, s1, 2);
            lS[mt][0] = lS[mt][0] * al0 + s0;
            lS[mt][1] = lS[mt][1] * al1 + s1;
#pragma unroll
            for (int nt = 0; nt < 8; nt++) {
                Of[mt][nt][0] *= al0; Of[mt][nt][1] *= al0;
                Of[mt][nt][2] *= al1; Of[mt][nt][3] *= al1;
            }
        }

        // ---- O += P V : V fragments shared across both mt tiles ----
#pragma unroll
        for (int kc = 0; kc < 8; kc++) {
            uint32_t pa[2][4];
#pragma unroll
            for (int mt = 0; mt < 2; mt++) {
                float u0 = __shfl_sync(0xffffffffu, Sa[mt][kc][0], srcA);
                float u1 = __shfl_sync(0xffffffffu, Sa[mt][kc][1], srcA);
                float u2 = __shfl_sync(0xffffffffu, Sa[mt][kc][2], srcA);
                float u3 = __shfl_sync(0xffffffffu, Sa[mt][kc][3], srcA);
                float v0 = __shfl_sync(0xffffffffu, Sa[mt][kc][0], srcB);
                float v1 = __shfl_sync(0xffffffffu, Sa[mt][kc][1], srcB);
                float v2 = __shfl_sync(0xffffffffu, Sa[mt][kc][2], srcB);
                float v3 = __shfl_sync(0xffffffffu, Sa[mt][kc][3], srcB);
                pa[mt][0] = fbits(tf32r(odd ? u1 : u0));
                pa[mt][1] = fbits(tf32r(odd ? u3 : u2));
                pa[mt][2] = fbits(tf32r(odd ? v1 : v0));
                pa[mt][3] = fbits(tf32r(odd ? v3 : v2));
            }
#pragma unroll
            for (int dnt = 0; dnt < 8; dnt++) {
                uint32_t bf[2];
                int d0 = 8 * dnt + l4;
                bf[0] = fbits(Vs[(8 * kc + lm4    ) * 68 + d0]);
                bf[1] = fbits(Vs[(8 * kc + lm4 + 4) * 68 + d0]);
                mma8(Of[0][dnt], pa[0], bf);
                mma8(Of[1][dnt], pa[1], bf);
            }
        }
        __syncthreads();
    }
#undef KVFILL

    // ---- epilogue: 1/l scale, tf32 round (feeds cp.async GEMM), store ----
#pragma unroll
    for (int mt = 0; mt < 2; mt++) {
        float i0 = 1.f / lS[mt][0], i1 = 1.f / lS[mt][1];
        int r = b * SEQ + qt * 256 + 32 * w + 16 * mt + l4;
#pragma unroll
        for (int dnt = 0; dnt < 8; dnt++) {
            int c = h * DHEAD + 8 * dnt + 2 * lm4;
            float* o0 = g_ao + (size_t)r * DIM + c;
            *(float2*)o0 = make_float2(tf32r(Of[mt][dnt][0] * i0),
                                       tf32r(Of[mt][dnt][1] * i0));
            float* o1 = o0 + (size_t)8 * DIM;
            *(float2*)o1 = make_float2(tf32r(Of[mt][dnt][2] * i1),
                                       tf32r(Of[mt][dnt][3] * i1));
        }
    }
}

// ---------------------------------------------------------------------------
extern "C" void kernel_launch(void* const* d_in, const int* in_sizes, int n_in,
                              void* d_out, int out_size) {
    (void)in_sizes; (void)n_in; (void)out_size;
    const float* x    = (const float*)d_in[0];
    const float* ln_s = (const float*)d_in[1];
    const float* ln_b = (const float*)d_in[2];
    const float* Wq   = (const float*)d_in[3];
    const float* Wkv  = (const float*)d_in[4];
    const float* qn_s = (const float*)d_in[5];
    const float* qn_b = (const float*)d_in[6];
    const float* kn_s = (const float*)d_in[7];
    const float* kn_b = (const float*)d_in[8];
    const float* Wout = (const float*)d_in[9];
    float* out = (float*)d_out;

    cudaFuncSetAttribute(attn_kernel,
                         cudaFuncAttributeMaxDynamicSharedMemorySize, ATTN_SMEM);
    cudaFuncSetAttribute(gemm_qkv,
                         cudaFuncAttributeMaxDynamicSharedMemorySize, GEMM_SMEM);
    cudaFuncSetAttribute(gemm_out,
                         cudaFuncAttributeMaxDynamicSharedMemorySize, GEMM_SMEM);

    int wtot = (DIM * DIM + DIM * KVD + DIM * DIM) / 4;   // float4 units
    round_weights<<<(wtot + 255) / 256, 256>>>(Wq, Wkv, Wout);
    ln_rows<<<M_ROWS, 256>>>(x, ln_s, ln_b);
    gemm_qkv<<<dim3(12, M_ROWS / 128), 256, GEMM_SMEM>>>();
    head_ln<<<dim3(M_ROWS / 8, 24), 256>>>(qn_s, qn_b, kn_s, kn_b);
    attn_kernel<<<dim3(SEQ / 256, BATCH * HEADS), 256, ATTN_SMEM>>>();
    gemm_out<<<dim3(DIM / 128, M_ROWS / 128), 256, GEMM_SMEM>>>(out);
}

// round 15
// speedup vs baseline: 1.0303x; 1.0303x over previous
#include <cuda_runtime.h>
#include <math_constants.h>
#include <cstdint>

#define BATCH  4
#define SEQ    2048
#define DIM    1024
#define HEADS  16
#define GROUPS 4
#define DHEAD  64
#define KVD    512
#define M_ROWS (BATCH*SEQ)      /* 8192 */
#define QKV_N  (DIM + KVD)      /* 1536 */

// Scratch (allocation-free rule: __device__ globals). All tf32-pre-rounded.
__device__ float g_xn  [M_ROWS * DIM];
__device__ float g_qkv [M_ROWS * QKV_N];
__device__ float g_ao  [M_ROWS * DIM];
__device__ float g_wq  [DIM * DIM];
__device__ float g_wkv [DIM * KVD];
__device__ float g_wout[DIM * DIM];

// ---------------------------------------------------------------------------
// helpers
// ---------------------------------------------------------------------------
__device__ __forceinline__ float tf32r(float x) {
    uint32_t u;
    asm("cvt.rna.tf32.f32 %0, %1;" : "=r"(u) : "f"(x));
    return __uint_as_float(u);
}
__device__ __forceinline__ float4 tf32r4(float4 f) {
    f.x = tf32r(f.x); f.y = tf32r(f.y); f.z = tf32r(f.z); f.w = tf32r(f.w);
    return f;
}
__device__ __forceinline__ void mma8(float* c, const uint32_t* a, const uint32_t* b) {
    asm volatile(
        "mma.sync.aligned.m16n8k8.row.col.f32.tf32.tf32.f32 "
        "{%0,%1,%2,%3}, {%4,%5,%6,%7}, {%8,%9}, {%0,%1,%2,%3};\n"
        : "+f"(c[0]), "+f"(c[1]), "+f"(c[2]), "+f"(c[3])
        : "r"(a[0]), "r"(a[1]), "r"(a[2]), "r"(a[3]), "r"(b[0]), "r"(b[1]));
}
__device__ __forceinline__ uint32_t fbits(float x) { return __float_as_uint(x); }

__device__ __forceinline__ void cpa16(uint32_t dst, const float* src) {
    asm volatile("cp.async.cg.shared.global [%0], [%1], 16;\n" :: "r"(dst), "l"(src));
}
#define CP_COMMIT() asm volatile("cp.async.commit_group;\n" ::: "memory")
template<int N> __device__ __forceinline__ void cp_wait() {
    asm volatile("cp.async.wait_group %0;\n" :: "n"(N) : "memory");
}

#define SCALE_LOG2E 0.18033688011112042f   /* 0.125 * log2(e) */

// ---------------------------------------------------------------------------
// Kernel 0: round weights into tf32 copies
// ---------------------------------------------------------------------------
__global__ void __launch_bounds__(256) round_weights(const float* __restrict__ Wq,
                                                     const float* __restrict__ Wkv,
                                                     const float* __restrict__ Wout) {
    int i = (blockIdx.x * 256 + threadIdx.x) * 4;
    const int NQ = DIM * DIM, NKV = DIM * KVD;
    if (i < NQ) {
        *(float4*)(g_wq + i) = tf32r4(*(const float4*)(Wq + i));
    } else if (i < NQ + NKV) {
        int j = i - NQ;
        *(float4*)(g_wkv + j) = tf32r4(*(const float4*)(Wkv + j));
    } else {
        int j = i - NQ - NKV;
        if (j < DIM * DIM)
            *(float4*)(g_wout + j) = tf32r4(*(const float4*)(Wout + j));
    }
}

// ---------------------------------------------------------------------------
// Kernel 1: row LayerNorm over DIM=1024, tf32-rounded output
// ---------------------------------------------------------------------------
__global__ void __launch_bounds__(256) ln_rows(const float* __restrict__ x,
                                               const float* __restrict__ sc,
                                               const float* __restrict__ bi) {
    int row = blockIdx.x;
    const float* xr = x + (size_t)row * DIM;
    float v[4];
    float s = 0.f, s2 = 0.f;
#pragma unroll
    for (int i = 0; i < 4; i++) {
        v[i] = xr[threadIdx.x + i * 256];
        s += v[i]; s2 += v[i] * v[i];
    }
    __shared__ float rs[8], rq[8];
#pragma unroll
    for (int o = 16; o; o >>= 1) {
        s  += __shfl_xor_sync(0xffffffffu, s,  o);
        s2 += __shfl_xor_sync(0xffffffffu, s2, o);
    }
    int warp = threadIdx.x >> 5, lane = threadIdx.x & 31;
    if (!lane) { rs[warp] = s; rq[warp] = s2; }
    __syncthreads();
    if (threadIdx.x == 0) {
        float a = 0.f, b = 0.f;
#pragma unroll
        for (int w = 0; w < 8; w++) { a += rs[w]; b += rq[w]; }
        rs[0] = a; rq[0] = b;
    }
    __syncthreads();
    float mu = rs[0] * (1.f / DIM);
    float r  = rsqrtf(rq[0] * (1.f / DIM) - mu * mu + 1e-6f);
    float* o = g_xn + (size_t)row * DIM;
#pragma unroll
    for (int i = 0; i < 4; i++) {
        int c = threadIdx.x + i * 256;
        o[c] = tf32r((v[i] - mu) * r * sc[c] + bi[c]);
    }
}

// ---------------------------------------------------------------------------
// tf32 GEMM: 128x128 tile, cp.async double-buffered, 8 warps (4x2)
// (reverted to the R12 best-measured configuration)
// ---------------------------------------------------------------------------
__device__ __forceinline__ void mmgemm(const float* __restrict__ A, int lda,
                                       const float* __restrict__ Bp, int ldb,
                                       float* __restrict__ C, int ldc,
                                       int rowbase, int colb, int colc) {
    __shared__ float As[2][128][20];
    __shared__ float Bs[2][16][136];
    int tid = threadIdx.x, lane = tid & 31, w = tid >> 5;
    int l4 = lane >> 2, lm4 = lane & 3;
    int m0w = 32 * (w & 3), n0w = 64 * (w >> 2);
    uint32_t aB = (uint32_t)__cvta_generic_to_shared(&As[0][0][0]);
    uint32_t bB = (uint32_t)__cvta_generic_to_shared(&Bs[0][0][0]);

    float Cf[2][8][4];
#pragma unroll
    for (int mt = 0; mt < 2; mt++)
#pragma unroll
        for (int nt = 0; nt < 8; nt++)
#pragma unroll
            for (int i = 0; i < 4; i++) Cf[mt][nt][i] = 0.f;

    const int NIT = DIM / 16;   // K = 1024 for both GEMMs

#define GFILL(k0, st)                                                          \
    {                                                                          \
        _Pragma("unroll")                                                      \
        for (int t = 0; t < 2; t++) {                                          \
            int idx = tid + t * 256;                                           \
            int ra = idx >> 2, ca = (idx & 3) * 4;                             \
            cpa16(aB + (uint32_t)((st) * 2560 + ra * 20 + ca) * 4,             \
                  A + (size_t)(rowbase + ra) * lda + (k0) + ca);               \
            int rb = idx >> 5, cb = (idx & 31) * 4;                            \
            cpa16(bB + (uint32_t)((st) * 2176 + rb * 136 + cb) * 4,            \
                  Bp + (size_t)((k0) + rb) * ldb + colb + cb);                 \
        }                                                                      \
        CP_COMMIT();                                                           \
    }

    GFILL(0, 0);
    for (int it = 0; it < NIT; it++) {
        int s = it & 1;
        if (it + 1 < NIT) { GFILL((it + 1) * 16, s ^ 1); cp_wait<1>(); }
        else              { cp_wait<0>(); }
        __syncthreads();
#pragma unroll
        for (int ks = 0; ks < 2; ks++) {
            uint32_t af[2][4];
#pragma unroll
            for (int mt = 0; mt < 2; mt++) {
                int m = m0w + 16 * mt;
                af[mt][0] = fbits(As[s][m + l4    ][8 * ks + lm4]);
                af[mt][1] = fbits(As[s][m + l4 + 8][8 * ks + lm4]);
                af[mt][2] = fbits(As[s][m + l4    ][8 * ks + lm4 + 4]);
                af[mt][3] = fbits(As[s][m + l4 + 8][8 * ks + lm4 + 4]);
            }
#pragma unroll
            for (int nt = 0; nt < 8; nt++) {
                uint32_t bf[2];
                bf[0] = fbits(Bs[s][8 * ks + lm4    ][n0w + 8 * nt + l4]);
                bf[1] = fbits(Bs[s][8 * ks + lm4 + 4][n0w + 8 * nt + l4]);
                mma8(Cf[0][nt], af[0], bf);
                mma8(Cf[1][nt], af[1], bf);
            }
        }
        __syncthreads();
    }
#undef GFILL
#pragma unroll
    for (int mt = 0; mt < 2; mt++)
#pragma unroll
        for (int nt = 0; nt < 8; nt++) {
            int r = rowbase + m0w + 16 * mt + l4;
            int c = colc + n0w + 8 * nt + 2 * lm4;
            *(float2*)&C[(size_t)r * ldc + c] =
                make_float2(Cf[mt][nt][0], Cf[mt][nt][1]);
            *(float2*)&C[(size_t)(r + 8) * ldc + c] =
                make_float2(Cf[mt][nt][2], Cf[mt][nt][3]);
        }
}

__global__ void __launch_bounds__(256) gemm_qkv() {
    int nb = blockIdx.x;
    int rb = blockIdx.y * 128;
    const float* Bp; int ldb, colb;
    if (nb < 8) { Bp = g_wq;  ldb = DIM; colb = nb * 128; }
    else        { Bp = g_wkv; ldb = KVD; colb = (nb - 8) * 128; }
    mmgemm(g_xn, DIM, Bp, ldb, g_qkv, QKV_N, rb, colb, nb * 128);
}

__global__ void __launch_bounds__(256) gemm_out(float* __restrict__ out) {
    mmgemm(g_ao, DIM, g_wout, DIM, out, DIM,
           blockIdx.y * 128, blockIdx.x * 128, blockIdx.x * 128);
}

// ---------------------------------------------------------------------------
// Kernel 3: per-head LN, warp-per-(row,seg), 256-thread blocks.
// seg 0..15 = q heads (x 0.125*log2e), 16..19 = k groups, 20..23 = v (round only)
// ---------------------------------------------------------------------------
__global__ void __launch_bounds__(256) head_ln(const float* __restrict__ qs,
                                               const float* __restrict__ qb,
                                               const float* __restrict__ ks,
                                               const float* __restrict__ kb) {
    int w = threadIdx.x >> 5, lane = threadIdx.x & 31;
    int row = blockIdx.x * 8 + w, seg = blockIdx.y;
    if (seg >= 20) {
        float* p = g_qkv + (size_t)row * QKV_N + DIM + KVD / 2 + (seg - 20) * DHEAD;
        p[lane]      = tf32r(p[lane]);
        p[lane + 32] = tf32r(p[lane + 32]);
        return;
    }
    bool isq = seg < 16;
    int col0 = isq ? seg * DHEAD : DIM + (seg - 16) * DHEAD;
    const float* sc = isq ? qs : ks;
    const float* bb = isq ? qb : kb;
    float* p = g_qkv + (size_t)row * QKV_N + col0;
    float a = p[lane], c = p[lane + 32];
    float s = a + c, s2 = a * a + c * c;
#pragma unroll
    for (int o = 16; o; o >>= 1) {
        s  += __shfl_xor_sync(0xffffffffu, s,  o);
        s2 += __shfl_xor_sync(0xffffffffu, s2, o);
    }
    float mu = s * (1.f / 64.f);
    float r  = rsqrtf(s2 * (1.f / 64.f) - mu * mu + 1e-6f);
    float mult = isq ? SCALE_LOG2E : 1.0f;
    p[lane]      = tf32r(((a - mu) * r * sc[lane]      + bb[lane])      * mult);
    p[lane + 32] = tf32r(((c - mu) * r * sc[lane + 32] + bb[lane + 32]) * mult);
}

// ---------------------------------------------------------------------------
// Kernel 4: flash attention, tf32 mma, register-resident softmax.
// Block = 128 q rows x (b,h): 4 warps, each warp 32 q rows x ALL 64 keys
// (keeps the R12 per-warp crossbar sharing). Grid (16,64)=1024 blocks ->
// 6.9 waves (was 3.46), and 2 CTAs/SM overlap sync/fill stalls.
// ---------------------------------------------------------------------------
#define AT_STAGE (2 * 64 * 68)              /* floats per stage (K + V) */
#define ATTN_SMEM (2 * AT_STAGE * 4)        /* 69632 bytes */

__global__ void __launch_bounds__(128, 2) attn_kernel() {
    extern __shared__ float sm[];
    int tid = threadIdx.x, lane = tid & 31, w = tid >> 5;   // w in 0..3
    int l4 = lane >> 2, lm4 = lane & 3;
    int qt = blockIdx.x, bh = blockIdx.y;
    int b = bh >> 4, h = bh & 15, g = h >> 2;
    uint32_t smb = (uint32_t)__cvta_generic_to_shared(sm);

    // ---- stage Q (128 rows x 64) into stage-0 region, hoist frags ----
    const float* qsrc = g_qkv + (size_t)(b * SEQ + qt * 128) * QKV_N + h * DHEAD;
#pragma unroll
    for (int i = 0; i < 16; i++) {
        int idx = tid + i * 128;                 // 0..2047
        int r = idx >> 4, c = (idx & 15) * 4;
        cpa16(smb + (uint32_t)(r * 68 + c) * 4, qsrc + (size_t)r * QKV_N + c);
    }
    CP_COMMIT(); cp_wait<0>();
    __syncthreads();

    uint32_t Qf[2][8][4];
#pragma unroll
    for (int mt = 0; mt < 2; mt++) {
        int r0 = 32 * w + 16 * mt + l4;
#pragma unroll
        for (int ks = 0; ks < 8; ks++) {
            Qf[mt][ks][0] = fbits(sm[(r0    ) * 68 + 8 * ks + lm4]);
            Qf[mt][ks][1] = fbits(sm[(r0 + 8) * 68 + 8 * ks + lm4]);
            Qf[mt][ks][2] = fbits(sm[(r0    ) * 68 + 8 * ks + lm4 + 4]);
            Qf[mt][ks][3] = fbits(sm[(r0 + 8) * 68 + 8 * ks + lm4 + 4]);
        }
    }
    __syncthreads();

    const float* kb0 = g_qkv + (size_t)(b * SEQ) * QKV_N + DIM + g * DHEAD;
    const float* vb0 = kb0 + KVD / 2;

#define KVFILL(kt, st)                                                         \
    {                                                                          \
        const float* kbp = kb0 + (size_t)(kt) * 64 * QKV_N;                    \
        const float* vbp = vb0 + (size_t)(kt) * 64 * QKV_N;                    \
        uint32_t base = smb + (uint32_t)(st) * AT_STAGE * 4;                   \
        _Pragma("unroll")                                                      \
        for (int i = 0; i < 8; i++) {                                          \
            int idx = tid + i * 128;             /* 0..1023 */                 \
            int r = idx >> 4, c = (idx & 15) * 4;                              \
            cpa16(base + (uint32_t)(r * 68 + c) * 4,                           \
                  kbp + (size_t)r * QKV_N + c);                                \
            cpa16(base + (uint32_t)(64 * 68 + r * 68 + c) * 4,                 \
                  vbp + (size_t)r * QKV_N + c);                                \
        }                                                                      \
        CP_COMMIT();                                                           \
    }

    KVFILL(0, 0);

    float Of[2][8][4];
#pragma unroll
    for (int mt = 0; mt < 2; mt++)
#pragma unroll
        for (int nt = 0; nt < 8; nt++)
#pragma unroll
            for (int i = 0; i < 4; i++) Of[mt][nt][i] = 0.f;
    float mS[2][2], lS[2][2];
#pragma unroll
    for (int mt = 0; mt < 2; mt++) {
        mS[mt][0] = -CUDART_INF_F; mS[mt][1] = -CUDART_INF_F;
        lS[mt][0] = 0.f;           lS[mt][1] = 0.f;
    }

    int srcA = (l4 << 2) | (lm4 >> 1);
    int srcB = srcA + 2;
    bool odd = lm4 & 1;

    const int NT = SEQ / 64;
    for (int kt = 0; kt < NT; kt++) {
        int s = kt & 1;
        if (kt + 1 < NT) { KVFILL(kt + 1, s ^ 1); cp_wait<1>(); }
        else             { cp_wait<0>(); }
        __syncthreads();

        const float* Ks = sm + s * AT_STAGE;
        const float* Vs = Ks + 64 * 68;

        // ---- S = Q K^T; K fragments shared across both mt tiles ----
        float Sa[2][8][4];
#pragma unroll
        for (int mt = 0; mt < 2; mt++)
#pragma unroll
            for (int nt = 0; nt < 8; nt++)
#pragma unroll
                for (int i = 0; i < 4; i++) Sa[mt][nt][i] = 0.f;
#pragma unroll
        for (int ks = 0; ks < 8; ks++)
#pragma unroll
            for (int nt = 0; nt < 8; nt++) {
                uint32_t bf[2];
                int key = 8 * nt + l4;
                bf[0] = fbits(Ks[key * 68 + 8 * ks + lm4]);
                bf[1] = fbits(Ks[key * 68 + 8 * ks + lm4 + 4]);
                mma8(Sa[0][nt], Qf[0][ks], bf);
                mma8(Sa[1][nt], Qf[1][ks], bf);
            }

        // ---- warp-local online softmax, per mt tile ----
#pragma unroll
        for (int mt = 0; mt < 2; mt++) {
            float pm0 = -CUDART_INF_F, pm1 = -CUDART_INF_F;
#pragma unroll
            for (int nt = 0; nt < 8; nt++) {
                pm0 = fmaxf(pm0, fmaxf(Sa[mt][nt][0], Sa[mt][nt][1]));
                pm1 = fmaxf(pm1, fmaxf(Sa[mt][nt][2], Sa[mt][nt][3]));
            }
            pm0 = fmaxf(pm0, __shfl_xor_sync(0xffffffffu, pm0, 1));
            pm0 = fmaxf(pm0, __shfl_xor_sync(0xffffffffu, pm0, 2));
            pm1 = fmaxf(pm1, __shfl_xor_sync(0xffffffffu, pm1, 1));
            pm1 = fmaxf(pm1, __shfl_xor_sync(0xffffffffu, pm1, 2));
            float mn0 = fmaxf(mS[mt][0], pm0), mn1 = fmaxf(mS[mt][1], pm1);
            float al0 = exp2f(mS[mt][0] - mn0), al1 = exp2f(mS[mt][1] - mn1);
            mS[mt][0] = mn0; mS[mt][1] = mn1;
            float s0 = 0.f, s1 = 0.f;
#pragma unroll
            for (int nt = 0; nt < 8; nt++) {
                Sa[mt][nt][0] = exp2f(Sa[mt][nt][0] - mn0); s0 += Sa[mt][nt][0];
                Sa[mt][nt][1] = exp2f(Sa[mt][nt][1] - mn0); s0 += Sa[mt][nt][1];
                Sa[mt][nt][2] = exp2f(Sa[mt][nt][2] - mn1); s1 += Sa[mt][nt][2];
                Sa[mt][nt][3] = exp2f(Sa[mt][nt][3] - mn1); s1 += Sa[mt][nt][3];
            }
            s0 += __shfl_xor_sync(0xffffffffu, s0, 1);
            s0 += __shfl_xor_sync(0xffffffffu, s0, 2);
            s1 += __shfl_xor_sync(0xffffffffu, s1, 1);
            s1 += __shfl_xor_sync(0xffffffffu, s1, 2);
            lS[mt][0] = lS[mt][0] * al0 + s0;
            lS[mt][1] = lS[mt][1] * al1 + s1;
#pragma unroll
            for (int nt = 0; nt < 8; nt++) {
                Of[mt][nt][0] *= al0; Of[mt][nt][1] *= al0;
                Of[mt][nt][2] *= al1; Of[mt][nt][3] *= al1;
            }
        }

        // ---- O += P V : V fragments shared across both mt tiles ----
#pragma unroll
        for (int kc = 0; kc < 8; kc++) {
            uint32_t pa[2][4];
#pragma unroll
            for (int mt = 0; mt < 2; mt++) {
                float u0 = __shfl_sync(0xffffffffu, Sa[mt][kc][0], srcA);
                float u1 = __shfl_sync(0xffffffffu, Sa[mt][kc][1], srcA);
                float u2 = __shfl_sync(0xffffffffu, Sa[mt][kc][2], srcA);
                float u3 = __shfl_sync(0xffffffffu, Sa[mt][kc][3], srcA);
                float v0 = __shfl_sync(0xffffffffu, Sa[mt][kc][0], srcB);
                float v1 = __shfl_sync(0xffffffffu, Sa[mt][kc][1], srcB);
                float v2 = __shfl_sync(0xffffffffu, Sa[mt][kc][2], srcB);
                float v3 = __shfl_sync(0xffffffffu, Sa[mt][kc][3], srcB);
                pa[mt][0] = fbits(tf32r(odd ? u1 : u0));
                pa[mt][1] = fbits(tf32r(odd ? u3 : u2));
                pa[mt][2] = fbits(tf32r(odd ? v1 : v0));
                pa[mt][3] = fbits(tf32r(odd ? v3 : v2));
            }
#pragma unroll
            for (int dnt = 0; dnt < 8; dnt++) {
                uint32_t bf[2];
                int d0 = 8 * dnt + l4;
                bf[0] = fbits(Vs[(8 * kc + lm4    ) * 68 + d0]);
                bf[1] = fbits(Vs[(8 * kc + lm4 + 4) * 68 + d0]);
                mma8(Of[0][dnt], pa[0], bf);
                mma8(Of[1][dnt], pa[1], bf);
            }
        }
        __syncthreads();
    }
#undef KVFILL

    // ---- epilogue: 1/l scale, tf32 round (feeds cp.async GEMM), store ----
#pragma unroll
    for (int mt = 0; mt < 2; mt++) {
        float i0 = 1.f / lS[mt][0], i1 = 1.f / lS[mt][1];
        int r = b * SEQ + qt * 128 + 32 * w + 16 * mt + l4;
#pragma unroll
        for (int dnt = 0; dnt < 8; dnt++) {
            int c = h * DHEAD + 8 * dnt + 2 * lm4;
            float* o0 = g_ao + (size_t)r * DIM + c;
            *(float2*)o0 = make_float2(tf32r(Of[mt][dnt][0] * i0),
                                       tf32r(Of[mt][dnt][1] * i0));
            float* o1 = o0 + (size_t)8 * DIM;
            *(float2*)o1 = make_float2(tf32r(Of[mt][dnt][2] * i1),
                                       tf32r(Of[mt][dnt][3] * i1));
        }
    }
}

// ---------------------------------------------------------------------------
extern "C" void kernel_launch(void* const* d_in, const int* in_sizes, int n_in,
                              void* d_out, int out_size) {
    (void)in_sizes; (void)n_in; (void)out_size;
    const float* x    = (const float*)d_in[0];
    const float* ln_s = (const float*)d_in[1];
    const float* ln_b = (const float*)d_in[2];
    const float* Wq   = (const float*)d_in[3];
    const float* Wkv  = (const float*)d_in[4];
    const float* qn_s = (const float*)d_in[5];
    const float* qn_b = (const float*)d_in[6];
    const float* kn_s = (const float*)d_in[7];
    const float* kn_b = (const float*)d_in[8];
    const float* Wout = (const float*)d_in[9];
    float* out = (float*)d_out;

    cudaFuncSetAttribute(attn_kernel,
                         cudaFuncAttributeMaxDynamicSharedMemorySize, ATTN_SMEM);

    int wtot = (DIM * DIM + DIM * KVD + DIM * DIM) / 4;   // float4 units
    round_weights<<<(wtot + 255) / 256, 256>>>(Wq, Wkv, Wout);
    ln_rows<<<M_ROWS, 256>>>(x, ln_s, ln_b);
    gemm_qkv<<<dim3(12, M_ROWS / 128), 256>>>();
    head_ln<<<dim3(M_ROWS / 8, 24), 256>>>(qn_s, qn_b, kn_s, kn_b);
    attn_kernel<<<dim3(SEQ / 128, BATCH * HEADS), 128, ATTN_SMEM>>>();
    gemm_out<<<dim3(DIM / 128, M_ROWS / 128), 256>>>(out);
}

// round 16
// speedup vs baseline: 1.0438x; 1.0131x over previous
#include <cuda_runtime.h>
#include <math_constants.h>
#include <cstdint>

#define BATCH  4
#define SEQ    2048
#define DIM    1024
#define HEADS  16
#define GROUPS 4
#define DHEAD  64
#define KVD    512
#define M_ROWS (BATCH*SEQ)      /* 8192 */
#define QKV_N  (DIM + KVD)      /* 1536 */

// Scratch (allocation-free rule: __device__ globals). All tf32-pre-rounded.
__device__ float g_xn  [M_ROWS * DIM];
__device__ float g_qkv [M_ROWS * QKV_N];
__device__ float g_ao  [M_ROWS * DIM];
__device__ float g_wq  [DIM * DIM];
__device__ float g_wkv [DIM * KVD];
__device__ float g_wout[DIM * DIM];

// ---------------------------------------------------------------------------
// helpers
// ---------------------------------------------------------------------------
__device__ __forceinline__ float tf32r(float x) {
    uint32_t u;
    asm("cvt.rna.tf32.f32 %0, %1;" : "=r"(u) : "f"(x));
    return __uint_as_float(u);
}
__device__ __forceinline__ float4 tf32r4(float4 f) {
    f.x = tf32r(f.x); f.y = tf32r(f.y); f.z = tf32r(f.z); f.w = tf32r(f.w);
    return f;
}
__device__ __forceinline__ void mma8(float* c, const uint32_t* a, const uint32_t* b) {
    asm volatile(
        "mma.sync.aligned.m16n8k8.row.col.f32.tf32.tf32.f32 "
        "{%0,%1,%2,%3}, {%4,%5,%6,%7}, {%8,%9}, {%0,%1,%2,%3};\n"
        : "+f"(c[0]), "+f"(c[1]), "+f"(c[2]), "+f"(c[3])
        : "r"(a[0]), "r"(a[1]), "r"(a[2]), "r"(a[3]), "r"(b[0]), "r"(b[1]));
}
__device__ __forceinline__ uint32_t fbits(float x) { return __float_as_uint(x); }

__device__ __forceinline__ void cpa16(uint32_t dst, const float* src) {
    asm volatile("cp.async.cg.shared.global [%0], [%1], 16;\n" :: "r"(dst), "l"(src));
}
#define CP_COMMIT() asm volatile("cp.async.commit_group;\n" ::: "memory")
template<int N> __device__ __forceinline__ void cp_wait() {
    asm volatile("cp.async.wait_group %0;\n" :: "n"(N) : "memory");
}

#define SCALE_LOG2E 0.18033688011112042f   /* 0.125 * log2(e) */

// ---------------------------------------------------------------------------
// Kernel 1: fused pre-pass. blocks [0, M_ROWS): row LayerNorm (tf32 out).
// blocks [M_ROWS, M_ROWS+2560): tf32-round weights into g_w* copies.
// (merging removes one launch and shifts attn into the ncu capture slot)
// ---------------------------------------------------------------------------
#define RW_BLOCKS 2560   /* (1024*1024 + 1024*512 + 1024*1024)/4/256 */

__global__ void __launch_bounds__(256) pre_pass(const float* __restrict__ x,
                                                const float* __restrict__ sc,
                                                const float* __restrict__ bi,
                                                const float* __restrict__ Wq,
                                                const float* __restrict__ Wkv,
                                                const float* __restrict__ Wout) {
    if (blockIdx.x >= M_ROWS) {
        int i = ((blockIdx.x - M_ROWS) * 256 + threadIdx.x) * 4;
        const int NQ = DIM * DIM, NKV = DIM * KVD;
        if (i < NQ) {
            *(float4*)(g_wq + i) = tf32r4(*(const float4*)(Wq + i));
        } else if (i < NQ + NKV) {
            int j = i - NQ;
            *(float4*)(g_wkv + j) = tf32r4(*(const float4*)(Wkv + j));
        } else {
            int j = i - NQ - NKV;
            if (j < DIM * DIM)
                *(float4*)(g_wout + j) = tf32r4(*(const float4*)(Wout + j));
        }
        return;
    }
    int row = blockIdx.x;
    const float* xr = x + (size_t)row * DIM;
    float v[4];
    float s = 0.f, s2 = 0.f;
#pragma unroll
    for (int i = 0; i < 4; i++) {
        v[i] = xr[threadIdx.x + i * 256];
        s += v[i]; s2 += v[i] * v[i];
    }
    __shared__ float rs[8], rq[8];
#pragma unroll
    for (int o = 16; o; o >>= 1) {
        s  += __shfl_xor_sync(0xffffffffu, s,  o);
        s2 += __shfl_xor_sync(0xffffffffu, s2, o);
    }
    int warp = threadIdx.x >> 5, lane = threadIdx.x & 31;
    if (!lane) { rs[warp] = s; rq[warp] = s2; }
    __syncthreads();
    if (threadIdx.x == 0) {
        float a = 0.f, b = 0.f;
#pragma unroll
        for (int w = 0; w < 8; w++) { a += rs[w]; b += rq[w]; }
        rs[0] = a; rq[0] = b;
    }
    __syncthreads();
    float mu = rs[0] * (1.f / DIM);
    float r  = rsqrtf(rq[0] * (1.f / DIM) - mu * mu + 1e-6f);
    float* o = g_xn + (size_t)row * DIM;
#pragma unroll
    for (int i = 0; i < 4; i++) {
        int c = threadIdx.x + i * 256;
        o[c] = tf32r((v[i] - mu) * r * sc[c] + bi[c]);
    }
}

// ---------------------------------------------------------------------------
// tf32 GEMM: 128x128 tile, cp.async double-buffered, 8 warps (4x2)
// (R12 best-measured configuration, unchanged)
// ---------------------------------------------------------------------------
__device__ __forceinline__ void mmgemm(const float* __restrict__ A, int lda,
                                       const float* __restrict__ Bp, int ldb,
                                       float* __restrict__ C, int ldc,
                                       int rowbase, int colb, int colc) {
    __shared__ float As[2][128][20];
    __shared__ float Bs[2][16][136];
    int tid = threadIdx.x, lane = tid & 31, w = tid >> 5;
    int l4 = lane >> 2, lm4 = lane & 3;
    int m0w = 32 * (w & 3), n0w = 64 * (w >> 2);
    uint32_t aB = (uint32_t)__cvta_generic_to_shared(&As[0][0][0]);
    uint32_t bB = (uint32_t)__cvta_generic_to_shared(&Bs[0][0][0]);

    float Cf[2][8][4];
#pragma unroll
    for (int mt = 0; mt < 2; mt++)
#pragma unroll
        for (int nt = 0; nt < 8; nt++)
#pragma unroll
            for (int i = 0; i < 4; i++) Cf[mt][nt][i] = 0.f;

    const int NIT = DIM / 16;   // K = 1024 for both GEMMs

#define GFILL(k0, st)                                                          \
    {                                                                          \
        _Pragma("unroll")                                                      \
        for (int t = 0; t < 2; t++) {                                          \
            int idx = tid + t * 256;                                           \
            int ra = idx >> 2, ca = (idx & 3) * 4;                             \
            cpa16(aB + (uint32_t)((st) * 2560 + ra * 20 + ca) * 4,             \
                  A + (size_t)(rowbase + ra) * lda + (k0) + ca);               \
            int rb = idx >> 5, cb = (idx & 31) * 4;                            \
            cpa16(bB + (uint32_t)((st) * 2176 + rb * 136 + cb) * 4,            \
                  Bp + (size_t)((k0) + rb) * ldb + colb + cb);                 \
        }                                                                      \
        CP_COMMIT();                                                           \
    }

    GFILL(0, 0);
    for (int it = 0; it < NIT; it++) {
        int s = it & 1;
        if (it + 1 < NIT) { GFILL((it + 1) * 16, s ^ 1); cp_wait<1>(); }
        else              { cp_wait<0>(); }
        __syncthreads();
#pragma unroll
        for (int ks = 0; ks < 2; ks++) {
            uint32_t af[2][4];
#pragma unroll
            for (int mt = 0; mt < 2; mt++) {
                int m = m0w + 16 * mt;
                af[mt][0] = fbits(As[s][m + l4    ][8 * ks + lm4]);
                af[mt][1] = fbits(As[s][m + l4 + 8][8 * ks + lm4]);
                af[mt][2] = fbits(As[s][m + l4    ][8 * ks + lm4 + 4]);
                af[mt][3] = fbits(As[s][m + l4 + 8][8 * ks + lm4 + 4]);
            }
#pragma unroll
            for (int nt = 0; nt < 8; nt++) {
                uint32_t bf[2];
                bf[0] = fbits(Bs[s][8 * ks + lm4    ][n0w + 8 * nt + l4]);
                bf[1] = fbits(Bs[s][8 * ks + lm4 + 4][n0w + 8 * nt + l4]);
                mma8(Cf[0][nt], af[0], bf);
                mma8(Cf[1][nt], af[1], bf);
            }
        }
        __syncthreads();
    }
#undef GFILL
#pragma unroll
    for (int mt = 0; mt < 2; mt++)
#pragma unroll
        for (int nt = 0; nt < 8; nt++) {
            int r = rowbase + m0w + 16 * mt + l4;
            int c = colc + n0w + 8 * nt + 2 * lm4;
            *(float2*)&C[(size_t)r * ldc + c] =
                make_float2(Cf[mt][nt][0], Cf[mt][nt][1]);
            *(float2*)&C[(size_t)(r + 8) * ldc + c] =
                make_float2(Cf[mt][nt][2], Cf[mt][nt][3]);
        }
}

__global__ void __launch_bounds__(256) gemm_qkv() {
    int nb = blockIdx.x;
    int rb = blockIdx.y * 128;
    const float* Bp; int ldb, colb;
    if (nb < 8) { Bp = g_wq;  ldb = DIM; colb = nb * 128; }
    else        { Bp = g_wkv; ldb = KVD; colb = (nb - 8) * 128; }
    mmgemm(g_xn, DIM, Bp, ldb, g_qkv, QKV_N, rb, colb, nb * 128);
}

__global__ void __launch_bounds__(256) gemm_out(float* __restrict__ out) {
    mmgemm(g_ao, DIM, g_wout, DIM, out, DIM,
           blockIdx.y * 128, blockIdx.x * 128, blockIdx.x * 128);
}

// ---------------------------------------------------------------------------
// Kernel 3: per-head LN, warp-per-(row,seg), 256-thread blocks.
// seg 0..15 = q heads (x 0.125*log2e), 16..19 = k groups, 20..23 = v (round only)
// ---------------------------------------------------------------------------
__global__ void __launch_bounds__(256) head_ln(const float* __restrict__ qs,
                                               const float* __restrict__ qb,
                                               const float* __restrict__ ks,
                                               const float* __restrict__ kb) {
    int w = threadIdx.x >> 5, lane = threadIdx.x & 31;
    int row = blockIdx.x * 8 + w, seg = blockIdx.y;
    if (seg >= 20) {
        float* p = g_qkv + (size_t)row * QKV_N + DIM + KVD / 2 + (seg - 20) * DHEAD;
        p[lane]      = tf32r(p[lane]);
        p[lane + 32] = tf32r(p[lane + 32]);
        return;
    }
    bool isq = seg < 16;
    int col0 = isq ? seg * DHEAD : DIM + (seg - 16) * DHEAD;
    const float* sc = isq ? qs : ks;
    const float* bb = isq ? qb : kb;
    float* p = g_qkv + (size_t)row * QKV_N + col0;
    float a = p[lane], c = p[lane + 32];
    float s = a + c, s2 = a * a + c * c;
#pragma unroll
    for (int o = 16; o; o >>= 1) {
        s  += __shfl_xor_sync(0xffffffffu, s,  o);
        s2 += __shfl_xor_sync(0xffffffffu, s2, o);
    }
    float mu = s * (1.f / 64.f);
    float r  = rsqrtf(s2 * (1.f / 64.f) - mu * mu + 1e-6f);
    float mult = isq ? SCALE_LOG2E : 1.0f;
    p[lane]      = tf32r(((a - mu) * r * sc[lane]      + bb[lane])      * mult);
    p[lane + 32] = tf32r(((c - mu) * r * sc[lane + 32] + bb[lane + 32]) * mult);
}

// ---------------------------------------------------------------------------
// Kernel 4: flash attention, tf32 mma, register-resident softmax.
// Block = 128 q rows x (b,h): 4 warps, each warp 32 q rows x ALL 64 keys.
// 3-stage cp.async KV pipeline, ONE __syncthreads per key tile:
//   wait(stage kt) -> sync (all warps done with kt-1) -> fill stage (kt+2)%3
//   -> compute stage kt%3 (no trailing sync; stages distinct mod 3).
// ---------------------------------------------------------------------------
#define AT_STAGE (2 * 64 * 68)              /* floats per stage (K + V) */
#define ATTN_SMEM (3 * AT_STAGE * 4)        /* 104448 bytes */

__global__ void __launch_bounds__(128, 2) attn_kernel() {
    extern __shared__ float sm[];
    int tid = threadIdx.x, lane = tid & 31, w = tid >> 5;   // w in 0..3
    int l4 = lane >> 2, lm4 = lane & 3;
    int qt = blockIdx.x, bh = blockIdx.y;
    int b = bh >> 4, h = bh & 15, g = h >> 2;
    uint32_t smb = (uint32_t)__cvta_generic_to_shared(sm);

    // ---- stage Q (128 rows x 64) into stage-0 region, hoist frags ----
    const float* qsrc = g_qkv + (size_t)(b * SEQ + qt * 128) * QKV_N + h * DHEAD;
#pragma unroll
    for (int i = 0; i < 16; i++) {
        int idx = tid + i * 128;                 // 0..2047
        int r = idx >> 4, c = (idx & 15) * 4;
        cpa16(smb + (uint32_t)(r * 68 + c) * 4, qsrc + (size_t)r * QKV_N + c);
    }
    CP_COMMIT(); cp_wait<0>();
    __syncthreads();

    uint32_t Qf[2][8][4];
#pragma unroll
    for (int mt = 0; mt < 2; mt++) {
        int r0 = 32 * w + 16 * mt + l4;
#pragma unroll
        for (int ks = 0; ks < 8; ks++) {
            Qf[mt][ks][0] = fbits(sm[(r0    ) * 68 + 8 * ks + lm4]);
            Qf[mt][ks][1] = fbits(sm[(r0 + 8) * 68 + 8 * ks + lm4]);
            Qf[mt][ks][2] = fbits(sm[(r0    ) * 68 + 8 * ks + lm4 + 4]);
            Qf[mt][ks][3] = fbits(sm[(r0 + 8) * 68 + 8 * ks + lm4 + 4]);
        }
    }
    __syncthreads();

    const float* kb0 = g_qkv + (size_t)(b * SEQ) * QKV_N + DIM + g * DHEAD;
    const float* vb0 = kb0 + KVD / 2;

#define KVFILL(kt, st)                                                         \
    {                                                                          \
        const float* kbp = kb0 + (size_t)(kt) * 64 * QKV_N;                    \
        const float* vbp = vb0 + (size_t)(kt) * 64 * QKV_N;                    \
        uint32_t base = smb + (uint32_t)(st) * AT_STAGE * 4;                   \
        _Pragma("unroll")                                                      \
        for (int i = 0; i < 8; i++) {                                          \
            int idx = tid + i * 128;             /* 0..1023 */                 \
            int r = idx >> 4, c = (idx & 15) * 4;                              \
            cpa16(base + (uint32_t)(r * 68 + c) * 4,                           \
                  kbp + (size_t)r * QKV_N + c);                                \
            cpa16(base + (uint32_t)(64 * 68 + r * 68 + c) * 4,                 \
                  vbp + (size_t)r * QKV_N + c);                                \
        }                                                                      \
        CP_COMMIT();                                                           \
    }

    KVFILL(0, 0);
    KVFILL(1, 1);

    float Of[2][8][4];
#pragma unroll
    for (int mt = 0; mt < 2; mt++)
#pragma unroll
        for (int nt = 0; nt < 8; nt++)
#pragma unroll
            for (int i = 0; i < 4; i++) Of[mt][nt][i] = 0.f;
    float mS[2][2], lS[2][2];
#pragma unroll
    for (int mt = 0; mt < 2; mt++) {
        mS[mt][0] = -CUDART_INF_F; mS[mt][1] = -CUDART_INF_F;
        lS[mt][0] = 0.f;           lS[mt][1] = 0.f;
    }

    int srcA = (l4 << 2) | (lm4 >> 1);
    int srcB = srcA + 2;
    bool odd = lm4 & 1;

    const int NT = SEQ / 64;
    int stage = 0;
    for (int kt = 0; kt < NT; kt++) {
        if (kt + 1 < NT) cp_wait<1>();   // stage kt complete (one group pending)
        else             cp_wait<0>();
        __syncthreads();                 // all warps done reading tile kt-1
        if (kt + 2 < NT) {
            int fs = stage + 2; if (fs >= 3) fs -= 3;
            KVFILL(kt + 2, fs);
        }

        const float* Ks = sm + stage * AT_STAGE;
        const float* Vs = Ks + 64 * 68;

        // ---- S = Q K^T; K fragments shared across both mt tiles ----
        float Sa[2][8][4];
#pragma unroll
        for (int mt = 0; mt < 2; mt++)
#pragma unroll
            for (int nt = 0; nt < 8; nt++)
#pragma unroll
                for (int i = 0; i < 4; i++) Sa[mt][nt][i] = 0.f;
#pragma unroll
        for (int ks = 0; ks < 8; ks++)
#pragma unroll
            for (int nt = 0; nt < 8; nt++) {
                uint32_t bf[2];
                int key = 8 * nt + l4;
                bf[0] = fbits(Ks[key * 68 + 8 * ks + lm4]);
                bf[1] = fbits(Ks[key * 68 + 8 * ks + lm4 + 4]);
                mma8(Sa[0][nt], Qf[0][ks], bf);
                mma8(Sa[1][nt], Qf[1][ks], bf);
            }

        // ---- warp-local online softmax, per mt tile ----
#pragma unroll
        for (int mt = 0; mt < 2; mt++) {
            float pm0 = -CUDART_INF_F, pm1 = -CUDART_INF_F;
#pragma unroll
            for (int nt = 0; nt < 8; nt++) {
                pm0 = fmaxf(pm0, fmaxf(Sa[mt][nt][0], Sa[mt][nt][1]));
                pm1 = fmaxf(pm1, fmaxf(Sa[mt][nt][2], Sa[mt][nt][3]));
            }
            pm0 = fmaxf(pm0, __shfl_xor_sync(0xffffffffu, pm0, 1));
            pm0 = fmaxf(pm0, __shfl_xor_sync(0xffffffffu, pm0, 2));
            pm1 = fmaxf(pm1, __shfl_xor_sync(0xffffffffu, pm1, 1));
            pm1 = fmaxf(pm1, __shfl_xor_sync(0xffffffffu, pm1, 2));
            float mn0 = fmaxf(mS[mt][0], pm0), mn1 = fmaxf(mS[mt][1], pm1);
            float al0 = exp2f(mS[mt][0] - mn0), al1 = exp2f(mS[mt][1] - mn1);
            mS[mt][0] = mn0; mS[mt][1] = mn1;
            float s0 = 0.f, s1 = 0.f;
#pragma unroll
            for (int nt = 0; nt < 8; nt++) {
                Sa[mt][nt][0] = exp2f(Sa[mt][nt][0] - mn0); s0 += Sa[mt][nt][0];
                Sa[mt][nt][1] = exp2f(Sa[mt][nt][1] - mn0); s0 += Sa[mt][nt][1];
                Sa[mt][nt][2] = exp2f(Sa[mt][nt][2] - mn1); s1 += Sa[mt][nt][2];
                Sa[mt][nt][3] = exp2f(Sa[mt][nt][3] - mn1); s1 += Sa[mt][nt][3];
            }
            s0 += __shfl_xor_sync(0xffffffffu, s0, 1);
            s0 += __shfl_xor_sync(0xffffffffu, s0, 2);
            s1 += __shfl_xor_sync(0xffffffffu, s1, 1);
            s1 += __shfl_xor_sync(0xffffffffu, s1, 2);
            lS[mt][0] = lS[mt][0] * al0 + s0;
            lS[mt][1] = lS[mt][1] * al1 + s1;
#pragma unroll
            for (int nt = 0; nt < 8; nt++) {
                Of[mt][nt][0] *= al0; Of[mt][nt][1] *= al0;
                Of[mt][nt][2] *= al1; Of[mt][nt][3] *= al1;
            }
        }

        // ---- O += P V : V fragments shared across both mt tiles ----
#pragma unroll
        for (int kc = 0; kc < 8; kc++) {
            uint32_t pa[2][4];
#pragma unroll
            for (int mt = 0; mt < 2; mt++) {
                float u0 = __shfl_sync(0xffffffffu, Sa[mt][kc][0], srcA);
                float u1 = __shfl_sync(0xffffffffu, Sa[mt][kc][1], srcA);
                float u2 = __shfl_sync(0xffffffffu, Sa[mt][kc][2], srcA);
                float u3 = __shfl_sync(0xffffffffu, Sa[mt][kc][3], srcA);
                float v0 = __shfl_sync(0xffffffffu, Sa[mt][kc][0], srcB);
                float v1 = __shfl_sync(0xffffffffu, Sa[mt][kc][1], srcB);
                float v2 = __shfl_sync(0xffffffffu, Sa[mt][kc][2], srcB);
                float v3 = __shfl_sync(0xffffffffu, Sa[mt][kc][3], srcB);
                pa[mt][0] = fbits(tf32r(odd ? u1 : u0));
                pa[mt][1] = fbits(tf32r(odd ? u3 : u2));
                pa[mt][2] = fbits(tf32r(odd ? v1 : v0));
                pa[mt][3] = fbits(tf32r(odd ? v3 : v2));
            }
#pragma unroll
            for (int dnt = 0; dnt < 8; dnt++) {
                uint32_t bf[2];
                int d0 = 8 * dnt + l4;
                bf[0] = fbits(Vs[(8 * kc + lm4    ) * 68 + d0]);
                bf[1] = fbits(Vs[(8 * kc + lm4 + 4) * 68 + d0]);
                mma8(Of[0][dnt], pa[0], bf);
                mma8(Of[1][dnt], pa[1], bf);
            }
        }
        if (++stage == 3) stage = 0;
    }
#undef KVFILL

    // ---- epilogue: 1/l scale, tf32 round (feeds cp.async GEMM), store ----
#pragma unroll
    for (int mt = 0; mt < 2; mt++) {
        float i0 = 1.f / lS[mt][0], i1 = 1.f / lS[mt][1];
        int r = b * SEQ + qt * 128 + 32 * w + 16 * mt + l4;
#pragma unroll
        for (int dnt = 0; dnt < 8; dnt++) {
            int c = h * DHEAD + 8 * dnt + 2 * lm4;
            float* o0 = g_ao + (size_t)r * DIM + c;
            *(float2*)o0 = make_float2(tf32r(Of[mt][dnt][0] * i0),
                                       tf32r(Of[mt][dnt][1] * i0));
            float* o1 = o0 + (size_t)8 * DIM;
            *(float2*)o1 = make_float2(tf32r(Of[mt][dnt][2] * i1),
                                       tf32r(Of[mt][dnt][3] * i1));
        }
    }
}

// ---------------------------------------------------------------------------
extern "C" void kernel_launch(void* const* d_in, const int* in_sizes, int n_in,
                              void* d_out, int out_size) {
    (void)in_sizes; (void)n_in; (void)out_size;
    const float* x    = (const float*)d_in[0];
    const float* ln_s = (const float*)d_in[1];
    const float* ln_b = (const float*)d_in[2];
    const float* Wq   = (const float*)d_in[3];
    const float* Wkv  = (const float*)d_in[4];
    const float* qn_s = (const float*)d_in[5];
    const float* qn_b = (const float*)d_in[6];
    const float* kn_s = (const float*)d_in[7];
    const float* kn_b = (const float*)d_in[8];
    const float* Wout = (const float*)d_in[9];
    float* out = (float*)d_out;

    cudaFuncSetAttribute(attn_kernel,
                         cudaFuncAttributeMaxDynamicSharedMemorySize, ATTN_SMEM);

    pre_pass<<<M_ROWS + RW_BLOCKS, 256>>>(x, ln_s, ln_b, Wq, Wkv, Wout);
    gemm_qkv<<<dim3(12, M_ROWS / 128), 256>>>();
    head_ln<<<dim3(M_ROWS / 8, 24), 256>>>(qn_s, qn_b, kn_s, kn_b);
    attn_kernel<<<dim3(SEQ / 128, BATCH * HEADS), 128, ATTN_SMEM>>>();
    gemm_out<<<dim3(DIM / 128, M_ROWS / 128), 256>>>(out);
}